// round 1
// baseline (speedup 1.0000x reference)
#include <cuda_runtime.h>
#include <math.h>

#define NN   300000
#define NE   299999
#define NA   150000
#define DD   64
#define HH   128

// ---------------- scratch (static device globals; no allocs) ----------------
__device__ float g_h   [(size_t)NN * HH];
__device__ float g_xl  [(size_t)NN * HH];   // also reused as 'branch' [NA,HH]
__device__ float g_xr  [(size_t)NN * HH];   // also reused as 'hidden' [NA,HH]
__device__ float g_acc [(size_t)NN * HH];
__device__ float g_amax[NN];
__device__ float g_den [NN];
__device__ float g_ae  [NE];
__device__ float g_ctx [HH];
__device__ float g_cadd[HH];

// ---------------- generic GEMM: C[M,128] = A[M,K] @ W[K,128] + bias ----------
template <int K>
__global__ __launch_bounds__(256) void gemm_kernel(
    const float* __restrict__ A, const float* __restrict__ W,
    const float* __restrict__ bias, float* __restrict__ C, int M)
{
    extern __shared__ float sh[];
    float* Ws = sh;              // K*128
    float* As = sh + K * 128;    // 64*K
    const int tid = threadIdx.x;

    for (int i = tid; i < K * 32; i += 256)
        ((float4*)Ws)[i] = ((const float4*)W)[i];

    const int row0 = blockIdx.x * 64;
    for (int i = tid; i < 64 * (K / 4); i += 256) {
        int r = i / (K / 4), c4 = i % (K / 4);
        int gr = row0 + r;
        float4 v = make_float4(0.f, 0.f, 0.f, 0.f);
        if (gr < M) v = ((const float4*)(A + (size_t)gr * K))[c4];
        ((float4*)As)[i] = v;
    }
    __syncthreads();

    const int w = tid >> 5, ln = tid & 31;
    float acc[8][4];
#pragma unroll
    for (int i = 0; i < 8; ++i)
#pragma unroll
        for (int j = 0; j < 4; ++j) acc[i][j] = 0.f;

#pragma unroll 4
    for (int k = 0; k < K; ++k) {
        float w0 = Ws[k * 128 + ln];
        float w1 = Ws[k * 128 + ln + 32];
        float w2 = Ws[k * 128 + ln + 64];
        float w3 = Ws[k * 128 + ln + 96];
#pragma unroll
        for (int i = 0; i < 8; ++i) {
            float a = As[(w * 8 + i) * K + k];
            acc[i][0] += a * w0; acc[i][1] += a * w1;
            acc[i][2] += a * w2; acc[i][3] += a * w3;
        }
    }

    float b0 = bias[ln], b1 = bias[ln + 32], b2 = bias[ln + 64], b3 = bias[ln + 96];
#pragma unroll
    for (int i = 0; i < 8; ++i) {
        int gr = row0 + w * 8 + i;
        if (gr < M) {
            float* cp = C + (size_t)gr * 128;
            cp[ln]      = acc[i][0] + b0;
            cp[ln + 32] = acc[i][1] + b1;
            cp[ln + 64] = acc[i][2] + b2;
            cp[ln + 96] = acc[i][3] + b3;
        }
    }
}

// ------- gather-concat GEMM: row r = [A0[idx0[r] or r], A1[idx1[r]] or 0] (K=256) -------
__global__ __launch_bounds__(256) void gemm_cat_kernel(
    const float* __restrict__ A0, const int* __restrict__ idx0,
    const float* __restrict__ A1, const int* __restrict__ idx1,
    const float* __restrict__ W, const float* __restrict__ bias,
    float* __restrict__ C, int M, int relu)
{
    extern __shared__ float sh[];
    float* Ws = sh;                // 128*128 chunk
    float* As = sh + 128 * 128;    // 64*256
    const int tid = threadIdx.x;
    const int row0 = blockIdx.x * 64;

    for (int i = tid; i < 64 * 64; i += 256) {
        int r = i >> 6, c4 = i & 63;
        int gr = row0 + r;
        float4 v = make_float4(0.f, 0.f, 0.f, 0.f);
        if (gr < M) {
            if (c4 < 32) {
                int ri = idx0 ? idx0[gr] : gr;
                v = ((const float4*)(A0 + (size_t)ri * 128))[c4];
            } else {
                int ri = idx1[gr];
                if (ri >= 0)
                    v = ((const float4*)(A1 + (size_t)ri * 128))[c4 - 32];
            }
        }
        ((float4*)As)[i] = v;
    }

    const int w = tid >> 5, ln = tid & 31;
    float acc[8][4];
#pragma unroll
    for (int i = 0; i < 8; ++i)
#pragma unroll
        for (int j = 0; j < 4; ++j) acc[i][j] = 0.f;

    for (int kc = 0; kc < 2; ++kc) {
        __syncthreads();
        for (int i = tid; i < 128 * 32; i += 256)
            ((float4*)Ws)[i] = ((const float4*)(W + kc * 128 * 128))[i];
        __syncthreads();
#pragma unroll 4
        for (int k = 0; k < 128; ++k) {
            float w0 = Ws[k * 128 + ln];
            float w1 = Ws[k * 128 + ln + 32];
            float w2 = Ws[k * 128 + ln + 64];
            float w3 = Ws[k * 128 + ln + 96];
#pragma unroll
            for (int i = 0; i < 8; ++i) {
                float a = As[(w * 8 + i) * 256 + kc * 128 + k];
                acc[i][0] += a * w0; acc[i][1] += a * w1;
                acc[i][2] += a * w2; acc[i][3] += a * w3;
            }
        }
    }

    float b0 = bias[ln], b1 = bias[ln + 32], b2 = bias[ln + 64], b3 = bias[ln + 96];
#pragma unroll
    for (int i = 0; i < 8; ++i) {
        int gr = row0 + w * 8 + i;
        if (gr < M) {
            float v0 = acc[i][0] + b0, v1 = acc[i][1] + b1;
            float v2 = acc[i][2] + b2, v3 = acc[i][3] + b3;
            if (relu) {
                v0 = fmaxf(v0, 0.f); v1 = fmaxf(v1, 0.f);
                v2 = fmaxf(v2, 0.f); v3 = fmaxf(v3, 0.f);
            }
            float* cp = C + (size_t)gr * 128;
            cp[ln] = v0; cp[ln + 32] = v1; cp[ln + 64] = v2; cp[ln + 96] = v3;
        }
    }
}

// ---------------- GAT edge kernels ----------------
__device__ __forceinline__ void atomicMaxFloat(float* addr, float v)
{
    if (v >= 0.f) atomicMax((int*)addr, __float_as_int(v));
    else          atomicMin((unsigned int*)addr, __float_as_uint(v));
}

__global__ void init_kernel()
{
    size_t i = (size_t)blockIdx.x * blockDim.x + threadIdx.x;
    if (i < (size_t)NN * HH) g_acc[i] = 0.f;
    if (i < NN) { g_amax[i] = __int_as_float(0xff800000); g_den[i] = 0.f; }
}

__global__ void edge_score_kernel(const int* __restrict__ src, const int* __restrict__ dst,
                                  const float* __restrict__ att)
{
    int e = (int)(((size_t)blockIdx.x * blockDim.x + threadIdx.x) >> 5);
    if (e >= NE) return;
    int ln = threadIdx.x & 31;
    int s = src[e], d = dst[e];
    const float* xls = g_xl + (size_t)s * 128;
    const float* xrd = g_xr + (size_t)d * 128;
    float p = 0.f;
#pragma unroll
    for (int j = 0; j < 4; ++j) {
        int hh = ln + 32 * j;
        float v = xls[hh] + xrd[hh];
        v = v > 0.f ? v : 0.2f * v;
        p += v * att[hh];
    }
#pragma unroll
    for (int o = 16; o > 0; o >>= 1) p += __shfl_xor_sync(0xffffffffu, p, o);
    if (ln == 0) { g_ae[e] = p; atomicMaxFloat(&g_amax[d], p); }
}

__global__ void edge_exp_kernel(const int* __restrict__ dst)
{
    int e = (int)((size_t)blockIdx.x * blockDim.x + threadIdx.x);
    if (e >= NE) return;
    int d = dst[e];
    float ex = expf(g_ae[e] - g_amax[d]);
    g_ae[e] = ex;
    atomicAdd(&g_den[d], ex);
}

__global__ void edge_scatter_kernel(const int* __restrict__ src, const int* __restrict__ dst)
{
    int e = (int)(((size_t)blockIdx.x * blockDim.x + threadIdx.x) >> 5);
    if (e >= NE) return;
    int ln = threadIdx.x & 31;
    int s = src[e], d = dst[e];
    float alpha = g_ae[e] / (g_den[d] + 1e-16f);
    const float* xls = g_xl + (size_t)s * 128;
    float* accd = g_acc + (size_t)d * 128;
#pragma unroll
    for (int j = 0; j < 4; ++j) {
        int hh = ln + 32 * j;
        atomicAdd(&accd[hh], alpha * xls[hh]);
    }
}

__global__ void update_kernel(const float* __restrict__ bias)
{
    size_t i = (size_t)blockIdx.x * blockDim.x + threadIdx.x;
    if (i >= (size_t)NN * HH) return;
    int j = (int)(i & 127);
    float v = g_acc[i] + bias[j];
    g_h[i] += v > 0.f ? v : 0.f;
}

// ---------------- context precompute ----------------
__global__ void ctx_kernel(const float* __restrict__ focal, const float* __restrict__ W_seq,
                           const float* __restrict__ b_seq)
{
    int j = threadIdx.x;
    float s = b_seq[j];
    for (int d = 0; d < DD; ++d) s += focal[d] * W_seq[d * 128 + j];
    g_ctx[j] = s;
}

__global__ void cadd_kernel(const float* __restrict__ W_a1, const float* __restrict__ b_a1)
{
    int j = threadIdx.x;
    float s = b_a1[j];
    for (int k = 0; k < 128; ++k) s += g_ctx[k] * W_a1[(256 + k) * 128 + j];
    g_cadd[j] = s;
}

// ---------------- final dot: logits = hidden @ W_a2 + b_a2 ----------------
__global__ void dot_kernel(const float* __restrict__ Hd, const float* __restrict__ W2,
                           const float* __restrict__ b2, float* __restrict__ out)
{
    int r = (int)(((size_t)blockIdx.x * blockDim.x + threadIdx.x) >> 5);
    if (r >= NA) return;
    int ln = threadIdx.x & 31;
    const float* hr = Hd + (size_t)r * 128;
    float p = 0.f;
#pragma unroll
    for (int j = 0; j < 4; ++j) p += hr[ln + 32 * j] * W2[ln + 32 * j];
#pragma unroll
    for (int o = 16; o > 0; o >>= 1) p += __shfl_xor_sync(0xffffffffu, p, o);
    if (ln == 0) out[r] = p + b2[0];
}

// ---------------- launch ----------------
extern "C" void kernel_launch(void* const* d_in, const int* in_sizes, int n_in,
                              void* d_out, int out_size)
{
    const float* x       = (const float*)d_in[0];
    const int*   ei      = (const int*)  d_in[1];
    const float* focal   = (const float*)d_in[2];
    const int*   child   = (const int*)  d_in[3];
    const int*   parent  = (const int*)  d_in[4];
    const int*   timei   = (const int*)  d_in[5];
    const float* W_embed = (const float*)d_in[6];
    const float* b_embed = (const float*)d_in[7];
    const float* bu_Wl   = (const float*)d_in[8];
    const float* bu_bl   = (const float*)d_in[9];
    const float* bu_Wr   = (const float*)d_in[10];
    const float* bu_br   = (const float*)d_in[11];
    const float* bu_att  = (const float*)d_in[12];
    const float* bu_bias = (const float*)d_in[13];
    const float* td_Wl   = (const float*)d_in[14];
    const float* td_bl   = (const float*)d_in[15];
    const float* td_Wr   = (const float*)d_in[16];
    const float* td_br   = (const float*)d_in[17];
    const float* td_att  = (const float*)d_in[18];
    const float* td_bias = (const float*)d_in[19];
    const float* ttab    = (const float*)d_in[20];
    const float* W_comb  = (const float*)d_in[21];
    const float* b_comb  = (const float*)d_in[22];
    const float* W_a1    = (const float*)d_in[23];
    const float* b_a1    = (const float*)d_in[24];
    const float* W_a2    = (const float*)d_in[25];
    const float* b_a2    = (const float*)d_in[26];
    const float* W_seq   = (const float*)d_in[27];
    const float* b_seq   = (const float*)d_in[28];
    float* out = (float*)d_out;

    const int SM64  = (64 * 128 + 64 * 64) * 4;     // 48 KB
    const int SM128 = (128 * 128 + 64 * 128) * 4;   // 96 KB
    const int SMCAT = (128 * 128 + 64 * 256) * 4;   // 128 KB
    cudaFuncSetAttribute(gemm_kernel<64>,  cudaFuncAttributeMaxDynamicSharedMemorySize, SM64);
    cudaFuncSetAttribute(gemm_kernel<128>, cudaFuncAttributeMaxDynamicSharedMemorySize, SM128);
    cudaFuncSetAttribute(gemm_cat_kernel,  cudaFuncAttributeMaxDynamicSharedMemorySize, SMCAT);

    float *hp, *xlp, *xrp, *caddp;
    cudaGetSymbolAddress((void**)&hp,    g_h);
    cudaGetSymbolAddress((void**)&xlp,   g_xl);
    cudaGetSymbolAddress((void**)&xrp,   g_xr);
    cudaGetSymbolAddress((void**)&caddp, g_cadd);

    const int GEMM_BLKS_N = (NN + 63) / 64;
    const int GEMM_BLKS_A = (NA + 63) / 64;
    const int INIT_BLKS   = (int)(((size_t)NN * HH + 255) / 256);
    const int EDGE_W_BLKS = (NE + 7) / 8;      // warp-per-edge, 8 warps/block
    const int EDGE_T_BLKS = (NE + 255) / 256;  // thread-per-edge

    // 1) embed
    gemm_kernel<64><<<GEMM_BLKS_N, 256, SM64>>>(x, W_embed, b_embed, hp, NN);

    // 2) bottom-up GATv2: src = row1, dst = row0
    {
        const int* src = ei + NE;
        const int* dst = ei;
        gemm_kernel<128><<<GEMM_BLKS_N, 256, SM128>>>(hp, bu_Wl, bu_bl, xlp, NN);
        gemm_kernel<128><<<GEMM_BLKS_N, 256, SM128>>>(hp, bu_Wr, bu_br, xrp, NN);
        init_kernel<<<INIT_BLKS, 256>>>();
        edge_score_kernel<<<EDGE_W_BLKS, 256>>>(src, dst, bu_att);
        edge_exp_kernel<<<EDGE_T_BLKS, 256>>>(dst);
        edge_scatter_kernel<<<EDGE_W_BLKS, 256>>>(src, dst);
        update_kernel<<<INIT_BLKS, 256>>>(bu_bias);
    }

    // 3) top-down GATv2: src = row0, dst = row1
    {
        const int* src = ei;
        const int* dst = ei + NE;
        gemm_kernel<128><<<GEMM_BLKS_N, 256, SM128>>>(hp, td_Wl, td_bl, xlp, NN);
        gemm_kernel<128><<<GEMM_BLKS_N, 256, SM128>>>(hp, td_Wr, td_br, xrp, NN);
        init_kernel<<<INIT_BLKS, 256>>>();
        edge_score_kernel<<<EDGE_W_BLKS, 256>>>(src, dst, td_att);
        edge_exp_kernel<<<EDGE_T_BLKS, 256>>>(dst);
        edge_scatter_kernel<<<EDGE_W_BLKS, 256>>>(src, dst);
        update_kernel<<<INIT_BLKS, 256>>>(td_bias);
    }

    // 4) context fold: cadd = b_a1 + (focal@W_seq + b_seq) @ W_a1[256:384]
    ctx_kernel<<<1, 128>>>(focal, W_seq, b_seq);
    cadd_kernel<<<1, 128>>>(W_a1, b_a1);

    // 5) branch = [h[child], h[parent]|0] @ W_comb + b_comb   (into g_xl)
    gemm_cat_kernel<<<GEMM_BLKS_A, 256, SMCAT>>>(hp, child, hp, parent,
                                                 W_comb, b_comb, xlp, NA, 0);

    // 6) hidden = relu([branch, time_table[time_idx]] @ W_a1[0:256] + cadd)  (into g_xr)
    gemm_cat_kernel<<<GEMM_BLKS_A, 256, SMCAT>>>(xlp, nullptr, ttab, timei,
                                                 W_a1, caddp, xrp, NA, 1);

    // 7) logits
    dot_kernel<<<(NA + 7) / 8, 256>>>(xrp, W_a2, b_a2, out);
}

// round 2
// speedup vs baseline: 1.3330x; 1.3330x over previous
#include <cuda_runtime.h>
#include <math.h>
#include <stdint.h>

#define NN   300000
#define NE   299999
#define NA   150000
#define DD   64
#define HH   128

// ---------------- scratch (static device globals; no allocs) ----------------
__device__ float g_h   [(size_t)NN * HH];
__device__ float g_xl  [(size_t)NN * HH];   // also reused as 'branch' [NA,HH]
__device__ float g_xr  [(size_t)NN * HH];   // also reused as 'hidden' [NA,HH]
__device__ float g_acc [(size_t)NN * HH];
__device__ float g_amax[NN];
__device__ float g_den [NN];
__device__ float g_ae  [NE];
__device__ float g_ctx [HH];
__device__ float g_cadd[HH];

// ---------------- tf32 helpers ----------------
__device__ __forceinline__ uint32_t f2tf32(float f)
{
    uint32_t u;
    asm("cvt.rna.tf32.f32 %0, %1;" : "=r"(u) : "f"(f));
    return u;
}

__device__ __forceinline__ void mma_tf32(float* d, const uint32_t* a, const uint32_t* b)
{
    asm volatile(
        "mma.sync.aligned.m16n8k8.row.col.f32.tf32.tf32.f32 "
        "{%0,%1,%2,%3},{%4,%5,%6,%7},{%8,%9},{%0,%1,%2,%3};"
        : "+f"(d[0]), "+f"(d[1]), "+f"(d[2]), "+f"(d[3])
        : "r"(a[0]), "r"(a[1]), "r"(a[2]), "r"(a[3]), "r"(b[0]), "r"(b[1]));
}

// Block tile: 128 rows x 128 cols. 8 warps, warp tile 32x64 (2 Mfrags x 8 Nfrags).
#define BM 128
#define BN 128
#define WNP 136   // W smem pitch (floats): banks 8*tig+gid -> conflict-free

// ---------------- tf32 GEMM: C[M,128] = A[M,K] @ W[K,128] + bias --------------
template <int K, bool RELU>
__global__ __launch_bounds__(256) void mm_tf32(
    const float* __restrict__ A, const float* __restrict__ W,
    const float* __restrict__ bias, float* __restrict__ C, int M)
{
    constexpr int KP = K + 4;  // A smem pitch: banks 4*gid+tig -> conflict-free
    extern __shared__ float sh[];
    float* As = sh;              // BM x KP
    float* Ws = sh + BM * KP;    // K x WNP
    const int tid = threadIdx.x;
    const int row0 = blockIdx.x * BM;

    // stage W (K x 128) as tf32
    for (int i = tid; i < K * 32; i += 256) {
        int k = i >> 5, c4 = i & 31;
        float4 v = ((const float4*)W)[i];
        float* wp = Ws + k * WNP + c4 * 4;
        wp[0] = __uint_as_float(f2tf32(v.x));
        wp[1] = __uint_as_float(f2tf32(v.y));
        wp[2] = __uint_as_float(f2tf32(v.z));
        wp[3] = __uint_as_float(f2tf32(v.w));
    }
    // stage A tile (BM x K) as tf32
    constexpr int K4 = K / 4;
    for (int i = tid; i < BM * K4; i += 256) {
        int r = i / K4, c4 = i % K4;
        int gr = row0 + r;
        float4 v = make_float4(0.f, 0.f, 0.f, 0.f);
        if (gr < M) v = ((const float4*)(A + (size_t)gr * K))[c4];
        float* ap = As + r * KP + c4 * 4;
        ap[0] = __uint_as_float(f2tf32(v.x));
        ap[1] = __uint_as_float(f2tf32(v.y));
        ap[2] = __uint_as_float(f2tf32(v.z));
        ap[3] = __uint_as_float(f2tf32(v.w));
    }
    __syncthreads();

    const int wid = tid >> 5, lane = tid & 31;
    const int wm = wid & 3, wn = wid >> 2;           // warp tile origin (wm*32, wn*64)
    const int gid = lane >> 2, tig = lane & 3;

    float acc[2][8][4];
#pragma unroll
    for (int mf = 0; mf < 2; ++mf)
#pragma unroll
        for (int nf = 0; nf < 8; ++nf)
#pragma unroll
            for (int j = 0; j < 4; ++j) acc[mf][nf][j] = 0.f;

#pragma unroll
    for (int ks = 0; ks < K / 8; ++ks) {
        const int k0 = ks * 8;
        uint32_t a[2][4], b[8][2];
#pragma unroll
        for (int mf = 0; mf < 2; ++mf) {
            const float* ap = As + (wm * 32 + mf * 16 + gid) * KP + k0;
            a[mf][0] = __float_as_uint(ap[tig]);
            a[mf][1] = __float_as_uint(ap[8 * KP + tig]);
            a[mf][2] = __float_as_uint(ap[tig + 4]);
            a[mf][3] = __float_as_uint(ap[8 * KP + tig + 4]);
        }
#pragma unroll
        for (int nf = 0; nf < 8; ++nf) {
            const int c = wn * 64 + nf * 8 + gid;
            b[nf][0] = __float_as_uint(Ws[(k0 + tig) * WNP + c]);
            b[nf][1] = __float_as_uint(Ws[(k0 + tig + 4) * WNP + c]);
        }
#pragma unroll
        for (int mf = 0; mf < 2; ++mf)
#pragma unroll
            for (int nf = 0; nf < 8; ++nf)
                mma_tf32(acc[mf][nf], a[mf], b[nf]);
    }

    // epilogue
#pragma unroll
    for (int nf = 0; nf < 8; ++nf) {
        const int c = wn * 64 + nf * 8 + tig * 2;
        const float b0 = bias[c], b1 = bias[c + 1];
#pragma unroll
        for (int mf = 0; mf < 2; ++mf) {
            const int rbase = row0 + wm * 32 + mf * 16 + gid;
#pragma unroll
            for (int h = 0; h < 2; ++h) {
                const int r = rbase + h * 8;
                if (r < M) {
                    float v0 = acc[mf][nf][2 * h]     + b0;
                    float v1 = acc[mf][nf][2 * h + 1] + b1;
                    if (RELU) { v0 = fmaxf(v0, 0.f); v1 = fmaxf(v1, 0.f); }
                    float2* cp = (float2*)(C + (size_t)r * 128 + c);
                    *cp = make_float2(v0, v1);
                }
            }
        }
    }
}

// ------- gather-concat tf32 GEMM: row r = [A0[idx0[r] or r], A1[idx1[r]] or 0], K=256 -------
template <bool RELU>
__global__ __launch_bounds__(256) void mm_cat_tf32(
    const float* __restrict__ A0, const int* __restrict__ idx0,
    const float* __restrict__ A1, const int* __restrict__ idx1,
    const float* __restrict__ W, const float* __restrict__ bias,
    float* __restrict__ C, int M)
{
    constexpr int K  = 256;
    constexpr int KP = K + 4;
    extern __shared__ float sh[];
    float* As = sh;              // BM x KP
    float* Ws = sh + BM * KP;    // 128 x WNP (per K-chunk)
    const int tid = threadIdx.x;
    const int row0 = blockIdx.x * BM;

    // stage A tile: gathered concat rows, tf32
    for (int i = tid; i < BM * 64; i += 256) {
        int r = i >> 6, c4 = i & 63;
        int gr = row0 + r;
        float4 v = make_float4(0.f, 0.f, 0.f, 0.f);
        if (gr < M) {
            if (c4 < 32) {
                int ri = idx0 ? idx0[gr] : gr;
                v = ((const float4*)(A0 + (size_t)ri * 128))[c4];
            } else {
                int ri = idx1[gr];
                if (ri >= 0)
                    v = ((const float4*)(A1 + (size_t)ri * 128))[c4 - 32];
            }
        }
        float* ap = As + r * KP + c4 * 4;
        ap[0] = __uint_as_float(f2tf32(v.x));
        ap[1] = __uint_as_float(f2tf32(v.y));
        ap[2] = __uint_as_float(f2tf32(v.z));
        ap[3] = __uint_as_float(f2tf32(v.w));
    }

    const int wid = tid >> 5, lane = tid & 31;
    const int wm = wid & 3, wn = wid >> 2;
    const int gid = lane >> 2, tig = lane & 3;

    float acc[2][8][4];
#pragma unroll
    for (int mf = 0; mf < 2; ++mf)
#pragma unroll
        for (int nf = 0; nf < 8; ++nf)
#pragma unroll
            for (int j = 0; j < 4; ++j) acc[mf][nf][j] = 0.f;

    for (int kc = 0; kc < 2; ++kc) {
        __syncthreads();
        // stage W chunk (128 x 128) as tf32
        for (int i = tid; i < 128 * 32; i += 256) {
            int k = i >> 5, c4 = i & 31;
            float4 v = ((const float4*)(W + kc * 128 * 128))[i];
            float* wp = Ws + k * WNP + c4 * 4;
            wp[0] = __uint_as_float(f2tf32(v.x));
            wp[1] = __uint_as_float(f2tf32(v.y));
            wp[2] = __uint_as_float(f2tf32(v.z));
            wp[3] = __uint_as_float(f2tf32(v.w));
        }
        __syncthreads();

#pragma unroll
        for (int ks = 0; ks < 16; ++ks) {
            const int k0 = ks * 8;
            uint32_t a[2][4], b[8][2];
#pragma unroll
            for (int mf = 0; mf < 2; ++mf) {
                const float* ap = As + (wm * 32 + mf * 16 + gid) * KP + kc * 128 + k0;
                a[mf][0] = __float_as_uint(ap[tig]);
                a[mf][1] = __float_as_uint(ap[8 * KP + tig]);
                a[mf][2] = __float_as_uint(ap[tig + 4]);
                a[mf][3] = __float_as_uint(ap[8 * KP + tig + 4]);
            }
#pragma unroll
            for (int nf = 0; nf < 8; ++nf) {
                const int c = wn * 64 + nf * 8 + gid;
                b[nf][0] = __float_as_uint(Ws[(k0 + tig) * WNP + c]);
                b[nf][1] = __float_as_uint(Ws[(k0 + tig + 4) * WNP + c]);
            }
#pragma unroll
            for (int mf = 0; mf < 2; ++mf)
#pragma unroll
                for (int nf = 0; nf < 8; ++nf)
                    mma_tf32(acc[mf][nf], a[mf], b[nf]);
        }
    }

#pragma unroll
    for (int nf = 0; nf < 8; ++nf) {
        const int c = wn * 64 + nf * 8 + tig * 2;
        const float b0 = bias[c], b1 = bias[c + 1];
#pragma unroll
        for (int mf = 0; mf < 2; ++mf) {
            const int rbase = row0 + wm * 32 + mf * 16 + gid;
#pragma unroll
            for (int h = 0; h < 2; ++h) {
                const int r = rbase + h * 8;
                if (r < M) {
                    float v0 = acc[mf][nf][2 * h]     + b0;
                    float v1 = acc[mf][nf][2 * h + 1] + b1;
                    if (RELU) { v0 = fmaxf(v0, 0.f); v1 = fmaxf(v1, 0.f); }
                    float2* cp = (float2*)(C + (size_t)r * 128 + c);
                    *cp = make_float2(v0, v1);
                }
            }
        }
    }
}

// ---------------- GAT edge kernels ----------------
__device__ __forceinline__ void atomicMaxFloat(float* addr, float v)
{
    if (v >= 0.f) atomicMax((int*)addr, __float_as_int(v));
    else          atomicMin((unsigned int*)addr, __float_as_uint(v));
}

__global__ void init_kernel()
{
    size_t i = (size_t)blockIdx.x * blockDim.x + threadIdx.x;
    if (i < (size_t)NN * HH) g_acc[i] = 0.f;
    if (i < NN) { g_amax[i] = __int_as_float(0xff800000); g_den[i] = 0.f; }
}

__global__ void edge_score_kernel(const int* __restrict__ src, const int* __restrict__ dst,
                                  const float* __restrict__ att)
{
    int e = (int)(((size_t)blockIdx.x * blockDim.x + threadIdx.x) >> 5);
    if (e >= NE) return;
    int ln = threadIdx.x & 31;
    int s = src[e], d = dst[e];
    const float* xls = g_xl + (size_t)s * 128;
    const float* xrd = g_xr + (size_t)d * 128;
    float p = 0.f;
#pragma unroll
    for (int j = 0; j < 4; ++j) {
        int hh = ln + 32 * j;
        float v = xls[hh] + xrd[hh];
        v = v > 0.f ? v : 0.2f * v;
        p += v * att[hh];
    }
#pragma unroll
    for (int o = 16; o > 0; o >>= 1) p += __shfl_xor_sync(0xffffffffu, p, o);
    if (ln == 0) { g_ae[e] = p; atomicMaxFloat(&g_amax[d], p); }
}

__global__ void edge_exp_kernel(const int* __restrict__ dst)
{
    int e = (int)((size_t)blockIdx.x * blockDim.x + threadIdx.x);
    if (e >= NE) return;
    int d = dst[e];
    float ex = expf(g_ae[e] - g_amax[d]);
    g_ae[e] = ex;
    atomicAdd(&g_den[d], ex);
}

__global__ void edge_scatter_kernel(const int* __restrict__ src, const int* __restrict__ dst)
{
    int e = (int)(((size_t)blockIdx.x * blockDim.x + threadIdx.x) >> 5);
    if (e >= NE) return;
    int ln = threadIdx.x & 31;
    int s = src[e], d = dst[e];
    float alpha = g_ae[e] / (g_den[d] + 1e-16f);
    const float* xls = g_xl + (size_t)s * 128;
    float* accd = g_acc + (size_t)d * 128;
#pragma unroll
    for (int j = 0; j < 4; ++j) {
        int hh = ln + 32 * j;
        atomicAdd(&accd[hh], alpha * xls[hh]);
    }
}

__global__ void update_kernel(const float* __restrict__ bias)
{
    size_t i = (size_t)blockIdx.x * blockDim.x + threadIdx.x;
    if (i >= (size_t)NN * HH) return;
    int j = (int)(i & 127);
    float v = g_acc[i] + bias[j];
    g_h[i] += v > 0.f ? v : 0.f;
}

// ---------------- context precompute ----------------
__global__ void ctx_kernel(const float* __restrict__ focal, const float* __restrict__ W_seq,
                           const float* __restrict__ b_seq)
{
    int j = threadIdx.x;
    float s = b_seq[j];
    for (int d = 0; d < DD; ++d) s += focal[d] * W_seq[d * 128 + j];
    g_ctx[j] = s;
}

__global__ void cadd_kernel(const float* __restrict__ W_a1, const float* __restrict__ b_a1)
{
    int j = threadIdx.x;
    float s = b_a1[j];
    for (int k = 0; k < 128; ++k) s += g_ctx[k] * W_a1[(256 + k) * 128 + j];
    g_cadd[j] = s;
}

// ---------------- final dot: logits = hidden @ W_a2 + b_a2 ----------------
__global__ void dot_kernel(const float* __restrict__ Hd, const float* __restrict__ W2,
                           const float* __restrict__ b2, float* __restrict__ out)
{
    int r = (int)(((size_t)blockIdx.x * blockDim.x + threadIdx.x) >> 5);
    if (r >= NA) return;
    int ln = threadIdx.x & 31;
    const float* hr = Hd + (size_t)r * 128;
    float p = 0.f;
#pragma unroll
    for (int j = 0; j < 4; ++j) p += hr[ln + 32 * j] * W2[ln + 32 * j];
#pragma unroll
    for (int o = 16; o > 0; o >>= 1) p += __shfl_xor_sync(0xffffffffu, p, o);
    if (ln == 0) out[r] = p + b2[0];
}

// ---------------- launch ----------------
extern "C" void kernel_launch(void* const* d_in, const int* in_sizes, int n_in,
                              void* d_out, int out_size)
{
    const float* x       = (const float*)d_in[0];
    const int*   ei      = (const int*)  d_in[1];
    const float* focal   = (const float*)d_in[2];
    const int*   child   = (const int*)  d_in[3];
    const int*   parent  = (const int*)  d_in[4];
    const int*   timei   = (const int*)  d_in[5];
    const float* W_embed = (const float*)d_in[6];
    const float* b_embed = (const float*)d_in[7];
    const float* bu_Wl   = (const float*)d_in[8];
    const float* bu_bl   = (const float*)d_in[9];
    const float* bu_Wr   = (const float*)d_in[10];
    const float* bu_br   = (const float*)d_in[11];
    const float* bu_att  = (const float*)d_in[12];
    const float* bu_bias = (const float*)d_in[13];
    const float* td_Wl   = (const float*)d_in[14];
    const float* td_bl   = (const float*)d_in[15];
    const float* td_Wr   = (const float*)d_in[16];
    const float* td_br   = (const float*)d_in[17];
    const float* td_att  = (const float*)d_in[18];
    const float* td_bias = (const float*)d_in[19];
    const float* ttab    = (const float*)d_in[20];
    const float* W_comb  = (const float*)d_in[21];
    const float* b_comb  = (const float*)d_in[22];
    const float* W_a1    = (const float*)d_in[23];
    const float* b_a1    = (const float*)d_in[24];
    const float* W_a2    = (const float*)d_in[25];
    const float* b_a2    = (const float*)d_in[26];
    const float* W_seq   = (const float*)d_in[27];
    const float* b_seq   = (const float*)d_in[28];
    float* out = (float*)d_out;

    const int SM64  = (BM * (64 + 4)  + 64  * WNP) * 4;   //  ~69.6 KB
    const int SM128 = (BM * (128 + 4) + 128 * WNP) * 4;   // ~134.0 KB
    const int SMCAT = (BM * (256 + 4) + 128 * WNP) * 4;   // ~198.0 KB
    cudaFuncSetAttribute(mm_tf32<64, false>,  cudaFuncAttributeMaxDynamicSharedMemorySize, SM64);
    cudaFuncSetAttribute(mm_tf32<128, false>, cudaFuncAttributeMaxDynamicSharedMemorySize, SM128);
    cudaFuncSetAttribute(mm_cat_tf32<false>,  cudaFuncAttributeMaxDynamicSharedMemorySize, SMCAT);
    cudaFuncSetAttribute(mm_cat_tf32<true>,   cudaFuncAttributeMaxDynamicSharedMemorySize, SMCAT);

    float *hp, *xlp, *xrp, *caddp;
    cudaGetSymbolAddress((void**)&hp,    g_h);
    cudaGetSymbolAddress((void**)&xlp,   g_xl);
    cudaGetSymbolAddress((void**)&xrp,   g_xr);
    cudaGetSymbolAddress((void**)&caddp, g_cadd);

    const int GEMM_BLKS_N = (NN + BM - 1) / BM;
    const int GEMM_BLKS_A = (NA + BM - 1) / BM;
    const int INIT_BLKS   = (int)(((size_t)NN * HH + 255) / 256);
    const int EDGE_W_BLKS = (NE + 7) / 8;
    const int EDGE_T_BLKS = (NE + 255) / 256;

    // 1) embed
    mm_tf32<64, false><<<GEMM_BLKS_N, 256, SM64>>>(x, W_embed, b_embed, hp, NN);

    // 2) bottom-up GATv2: src = row1, dst = row0
    {
        const int* src = ei + NE;
        const int* dst = ei;
        mm_tf32<128, false><<<GEMM_BLKS_N, 256, SM128>>>(hp, bu_Wl, bu_bl, xlp, NN);
        mm_tf32<128, false><<<GEMM_BLKS_N, 256, SM128>>>(hp, bu_Wr, bu_br, xrp, NN);
        init_kernel<<<INIT_BLKS, 256>>>();
        edge_score_kernel<<<EDGE_W_BLKS, 256>>>(src, dst, bu_att);
        edge_exp_kernel<<<EDGE_T_BLKS, 256>>>(dst);
        edge_scatter_kernel<<<EDGE_W_BLKS, 256>>>(src, dst);
        update_kernel<<<INIT_BLKS, 256>>>(bu_bias);
    }

    // 3) top-down GATv2: src = row0, dst = row1
    {
        const int* src = ei;
        const int* dst = ei + NE;
        mm_tf32<128, false><<<GEMM_BLKS_N, 256, SM128>>>(hp, td_Wl, td_bl, xlp, NN);
        mm_tf32<128, false><<<GEMM_BLKS_N, 256, SM128>>>(hp, td_Wr, td_br, xrp, NN);
        init_kernel<<<INIT_BLKS, 256>>>();
        edge_score_kernel<<<EDGE_W_BLKS, 256>>>(src, dst, td_att);
        edge_exp_kernel<<<EDGE_T_BLKS, 256>>>(dst);
        edge_scatter_kernel<<<EDGE_W_BLKS, 256>>>(src, dst);
        update_kernel<<<INIT_BLKS, 256>>>(td_bias);
    }

    // 4) context fold: cadd = b_a1 + (focal@W_seq + b_seq) @ W_a1[256:384]
    ctx_kernel<<<1, 128>>>(focal, W_seq, b_seq);
    cadd_kernel<<<1, 128>>>(W_a1, b_a1);

    // 5) branch = [h[child], h[parent]|0] @ W_comb + b_comb   (into g_xl)
    mm_cat_tf32<false><<<GEMM_BLKS_A, 256, SMCAT>>>(hp, child, hp, parent,
                                                    W_comb, b_comb, xlp, NA);

    // 6) hidden = relu([branch, t_emb] @ W_a1[0:256] + cadd)  (into g_xr)
    mm_cat_tf32<true><<<GEMM_BLKS_A, 256, SMCAT>>>(xlp, nullptr, ttab, timei,
                                                   W_a1, caddp, xrp, NA);

    // 7) logits
    dot_kernel<<<(NA + 7) / 8, 256>>>(xrp, W_a2, b_a2, out);
}

// round 3
// speedup vs baseline: 1.9139x; 1.4358x over previous
#include <cuda_runtime.h>
#include <math.h>
#include <stdint.h>

#define NN   300000
#define NE   299999
#define NA   150000
#define DD   64
#define HH   128

// ---------------- scratch (static device globals; no allocs) ----------------
__device__ float g_h   [(size_t)NN * HH];
__device__ float g_xl  [(size_t)NN * HH];
__device__ float g_xr  [(size_t)NN * HH];
__device__ float g_acc [(size_t)NN * HH];
__device__ float g_amax[NN];
__device__ float g_den [NN];
__device__ float g_ae  [NE];
__device__ float g_ctx [HH];
__device__ float g_cadd[HH];

// ---------------- tf32 helpers ----------------
__device__ __forceinline__ uint32_t f2tf32(float f)
{
    uint32_t u;
    asm("cvt.rna.tf32.f32 %0, %1;" : "=r"(u) : "f"(f));
    return u;
}

__device__ __forceinline__ void mma_tf32(float* d, const uint32_t* a, const uint32_t* b)
{
    asm volatile(
        "mma.sync.aligned.m16n8k8.row.col.f32.tf32.tf32.f32 "
        "{%0,%1,%2,%3},{%4,%5,%6,%7},{%8,%9},{%0,%1,%2,%3};"
        : "+f"(d[0]), "+f"(d[1]), "+f"(d[2]), "+f"(d[3])
        : "r"(a[0]), "r"(a[1]), "r"(a[2]), "r"(a[3]), "r"(b[0]), "r"(b[1]));
}

#define BM  128
#define WNP 136   // W smem pitch: conflict-free for b-frag loads

// ---- shared fragment-compute macro body (warp tile 32x64: 2 Mfrag x 8 Nfrag) ----
__device__ __forceinline__ void mma_block_128(
    const float* As, int KP, int a_off, const float* Ws,
    int wm, int wn, int gid, int tig, float acc[2][8][4])
{
#pragma unroll
    for (int ks = 0; ks < 16; ++ks) {
        const int k0 = ks * 8;
        uint32_t a[2][4], b[8][2];
#pragma unroll
        for (int mf = 0; mf < 2; ++mf) {
            const float* ap = As + (wm * 32 + mf * 16 + gid) * KP + a_off + k0;
            a[mf][0] = __float_as_uint(ap[tig]);
            a[mf][1] = __float_as_uint(ap[8 * KP + tig]);
            a[mf][2] = __float_as_uint(ap[tig + 4]);
            a[mf][3] = __float_as_uint(ap[8 * KP + tig + 4]);
        }
#pragma unroll
        for (int nf = 0; nf < 8; ++nf) {
            const int c = wn * 64 + nf * 8 + gid;
            b[nf][0] = __float_as_uint(Ws[(k0 + tig) * WNP + c]);
            b[nf][1] = __float_as_uint(Ws[(k0 + tig + 4) * WNP + c]);
        }
#pragma unroll
        for (int mf = 0; mf < 2; ++mf)
#pragma unroll
            for (int nf = 0; nf < 8; ++nf)
                mma_tf32(acc[mf][nf], a[mf], b[nf]);
    }
}

// ---------------- embed GEMM: C[M,128] = A[M,64] @ W[64,128] + bias ----------
__global__ __launch_bounds__(256) void mm_embed(
    const float* __restrict__ A, const float* __restrict__ W,
    const float* __restrict__ bias, float* __restrict__ C, int M)
{
    constexpr int K = 64, KP = K + 4;
    extern __shared__ float sh[];
    float* As = sh;              // BM x KP
    float* Ws = sh + BM * KP;    // K x WNP
    const int tid = threadIdx.x;
    const int row0 = blockIdx.x * BM;

    for (int i = tid; i < K * 32; i += 256) {
        int k = i >> 5, c4 = i & 31;
        float4 v = ((const float4*)W)[i];
        float* wp = Ws + k * WNP + c4 * 4;
        wp[0] = __uint_as_float(f2tf32(v.x));
        wp[1] = __uint_as_float(f2tf32(v.y));
        wp[2] = __uint_as_float(f2tf32(v.z));
        wp[3] = __uint_as_float(f2tf32(v.w));
    }
    for (int i = tid; i < BM * 16; i += 256) {
        int r = i >> 4, c4 = i & 15;
        int gr = row0 + r;
        float4 v = make_float4(0.f, 0.f, 0.f, 0.f);
        if (gr < M) v = ((const float4*)(A + (size_t)gr * K))[c4];
        float* ap = As + r * KP + c4 * 4;
        ap[0] = __uint_as_float(f2tf32(v.x));
        ap[1] = __uint_as_float(f2tf32(v.y));
        ap[2] = __uint_as_float(f2tf32(v.z));
        ap[3] = __uint_as_float(f2tf32(v.w));
    }
    __syncthreads();

    const int wid = tid >> 5, lane = tid & 31;
    const int wm = wid & 3, wn = wid >> 2;
    const int gid = lane >> 2, tig = lane & 3;

    float acc[2][8][4];
#pragma unroll
    for (int mf = 0; mf < 2; ++mf)
#pragma unroll
        for (int nf = 0; nf < 8; ++nf)
#pragma unroll
            for (int j = 0; j < 4; ++j) acc[mf][nf][j] = 0.f;

#pragma unroll
    for (int ks = 0; ks < 8; ++ks) {
        const int k0 = ks * 8;
        uint32_t a[2][4], b[8][2];
#pragma unroll
        for (int mf = 0; mf < 2; ++mf) {
            const float* ap = As + (wm * 32 + mf * 16 + gid) * KP + k0;
            a[mf][0] = __float_as_uint(ap[tig]);
            a[mf][1] = __float_as_uint(ap[8 * KP + tig]);
            a[mf][2] = __float_as_uint(ap[tig + 4]);
            a[mf][3] = __float_as_uint(ap[8 * KP + tig + 4]);
        }
#pragma unroll
        for (int nf = 0; nf < 8; ++nf) {
            const int c = wn * 64 + nf * 8 + gid;
            b[nf][0] = __float_as_uint(Ws[(k0 + tig) * WNP + c]);
            b[nf][1] = __float_as_uint(Ws[(k0 + tig + 4) * WNP + c]);
        }
#pragma unroll
        for (int mf = 0; mf < 2; ++mf)
#pragma unroll
            for (int nf = 0; nf < 8; ++nf)
                mma_tf32(acc[mf][nf], a[mf], b[nf]);
    }

#pragma unroll
    for (int nf = 0; nf < 8; ++nf) {
        const int c = wn * 64 + nf * 8 + tig * 2;
        const float b0 = bias[c], b1 = bias[c + 1];
#pragma unroll
        for (int mf = 0; mf < 2; ++mf)
#pragma unroll
            for (int h = 0; h < 2; ++h) {
                const int r = row0 + wm * 32 + mf * 16 + h * 8 + gid;
                if (r < M)
                    *(float2*)(C + (size_t)r * 128 + c) =
                        make_float2(acc[mf][nf][2 * h] + b0, acc[mf][nf][2 * h + 1] + b1);
            }
    }
}

// ------- dual transform: Cl = A@Wl+bl, Cr = A@Wr+br (A staged once) -------
__global__ __launch_bounds__(256) void mm_dual(
    const float* __restrict__ A,
    const float* __restrict__ Wl, const float* __restrict__ bl, float* __restrict__ Cl,
    const float* __restrict__ Wr, const float* __restrict__ br, float* __restrict__ Cr,
    int M)
{
    constexpr int K = 128, KP = K + 4;
    extern __shared__ float sh[];
    float* As  = sh;                      // BM x KP
    float* Ws0 = sh + BM * KP;            // 128 x WNP
    float* Ws1 = Ws0 + 128 * WNP;         // 128 x WNP
    const int tid = threadIdx.x;
    const int row0 = blockIdx.x * BM;

    for (int i = tid; i < K * 32; i += 256) {
        int k = i >> 5, c4 = i & 31;
        float4 vl = ((const float4*)Wl)[i];
        float4 vr = ((const float4*)Wr)[i];
        float* w0 = Ws0 + k * WNP + c4 * 4;
        float* w1 = Ws1 + k * WNP + c4 * 4;
        w0[0] = __uint_as_float(f2tf32(vl.x)); w0[1] = __uint_as_float(f2tf32(vl.y));
        w0[2] = __uint_as_float(f2tf32(vl.z)); w0[3] = __uint_as_float(f2tf32(vl.w));
        w1[0] = __uint_as_float(f2tf32(vr.x)); w1[1] = __uint_as_float(f2tf32(vr.y));
        w1[2] = __uint_as_float(f2tf32(vr.z)); w1[3] = __uint_as_float(f2tf32(vr.w));
    }
    for (int i = tid; i < BM * 32; i += 256) {
        int r = i >> 5, c4 = i & 31;
        int gr = row0 + r;
        float4 v = make_float4(0.f, 0.f, 0.f, 0.f);
        if (gr < M) v = ((const float4*)(A + (size_t)gr * K))[c4];
        float* ap = As + r * KP + c4 * 4;
        ap[0] = __uint_as_float(f2tf32(v.x));
        ap[1] = __uint_as_float(f2tf32(v.y));
        ap[2] = __uint_as_float(f2tf32(v.z));
        ap[3] = __uint_as_float(f2tf32(v.w));
    }
    __syncthreads();

    const int wid = tid >> 5, lane = tid & 31;
    const int wm = wid & 3, wn = wid >> 2;
    const int gid = lane >> 2, tig = lane & 3;

    float acc[2][8][4];
#pragma unroll
    for (int ph = 0; ph < 2; ++ph) {
        const float* Ws   = ph ? Ws1 : Ws0;
        const float* bias = ph ? br  : bl;
        float* C          = ph ? Cr  : Cl;
#pragma unroll
        for (int mf = 0; mf < 2; ++mf)
#pragma unroll
            for (int nf = 0; nf < 8; ++nf)
#pragma unroll
                for (int j = 0; j < 4; ++j) acc[mf][nf][j] = 0.f;

        mma_block_128(As, KP, 0, Ws, wm, wn, gid, tig, acc);

#pragma unroll
        for (int nf = 0; nf < 8; ++nf) {
            const int c = wn * 64 + nf * 8 + tig * 2;
            const float b0 = bias[c], b1 = bias[c + 1];
#pragma unroll
            for (int mf = 0; mf < 2; ++mf)
#pragma unroll
                for (int h = 0; h < 2; ++h) {
                    const int r = row0 + wm * 32 + mf * 16 + h * 8 + gid;
                    if (r < M)
                        *(float2*)(C + (size_t)r * 128 + c) =
                            make_float2(acc[mf][nf][2 * h] + b0, acc[mf][nf][2 * h + 1] + b1);
                }
        }
    }
}

// ------- mega head: branch->hidden->logits, all fused -------
__global__ __launch_bounds__(256) void head_kernel(
    const float* __restrict__ hsrc, const int* __restrict__ child, const int* __restrict__ parent,
    const float* __restrict__ ttab, const int* __restrict__ timei,
    const float* __restrict__ W_comb, const float* __restrict__ b_comb,
    const float* __restrict__ W_a1, const float* __restrict__ cadd,
    const float* __restrict__ W_a2, const float* __restrict__ b_a2,
    float* __restrict__ out, int M)
{
    constexpr int KP = 260;
    extern __shared__ float sh[];
    float* As  = sh;                   // 128 x 260
    float* Ws  = sh + 128 * KP;        // 128 x 136
    float* red = Ws + 128 * WNP;       // 2 x 128
    const int tid = threadIdx.x;
    const int row0 = blockIdx.x * BM;

    // stage cat(h[child], h[parent]|0) as tf32
    for (int i = tid; i < BM * 64; i += 256) {
        int r = i >> 6, c4 = i & 63;
        int gr = row0 + r;
        float4 v = make_float4(0.f, 0.f, 0.f, 0.f);
        if (gr < M) {
            if (c4 < 32) {
                int ri = child[gr];
                v = ((const float4*)(hsrc + (size_t)ri * 128))[c4];
            } else {
                int ri = parent[gr];
                if (ri >= 0) v = ((const float4*)(hsrc + (size_t)ri * 128))[c4 - 32];
            }
        }
        float* ap = As + r * KP + c4 * 4;
        ap[0] = __uint_as_float(f2tf32(v.x));
        ap[1] = __uint_as_float(f2tf32(v.y));
        ap[2] = __uint_as_float(f2tf32(v.z));
        ap[3] = __uint_as_float(f2tf32(v.w));
    }

    const int wid = tid >> 5, lane = tid & 31;
    const int wm = wid & 3, wn = wid >> 2;
    const int gid = lane >> 2, tig = lane & 3;

    float acc[2][8][4];
#pragma unroll
    for (int mf = 0; mf < 2; ++mf)
#pragma unroll
        for (int nf = 0; nf < 8; ++nf)
#pragma unroll
            for (int j = 0; j < 4; ++j) acc[mf][nf][j] = 0.f;

    // GEMM1: branch = cat @ W_comb
    for (int kc = 0; kc < 2; ++kc) {
        __syncthreads();
        for (int i = tid; i < 128 * 32; i += 256) {
            int k = i >> 5, c4 = i & 31;
            float4 v = ((const float4*)(W_comb + kc * 128 * 128))[i];
            float* wp = Ws + k * WNP + c4 * 4;
            wp[0] = __uint_as_float(f2tf32(v.x));
            wp[1] = __uint_as_float(f2tf32(v.y));
            wp[2] = __uint_as_float(f2tf32(v.z));
            wp[3] = __uint_as_float(f2tf32(v.w));
        }
        __syncthreads();
        mma_block_128(As, KP, kc * 128, Ws, wm, wn, gid, tig, acc);
    }

    __syncthreads();  // all GEMM1 As reads complete before overwrite

    // epilogue1: branch(+b_comb) -> As cols [0,128) as tf32
#pragma unroll
    for (int nf = 0; nf < 8; ++nf) {
        const int c = wn * 64 + nf * 8 + tig * 2;
        const float b0 = b_comb[c], b1 = b_comb[c + 1];
#pragma unroll
        for (int mf = 0; mf < 2; ++mf)
#pragma unroll
            for (int h = 0; h < 2; ++h) {
                const int rl = wm * 32 + mf * 16 + h * 8 + gid;
                As[rl * KP + c]     = __uint_as_float(f2tf32(acc[mf][nf][2 * h]     + b0));
                As[rl * KP + c + 1] = __uint_as_float(f2tf32(acc[mf][nf][2 * h + 1] + b1));
            }
    }
    // stage t_emb -> As cols [128,256)
    for (int i = tid; i < BM * 32; i += 256) {
        int r = i >> 5, c4 = i & 31;
        int gr = row0 + r;
        float4 v = make_float4(0.f, 0.f, 0.f, 0.f);
        if (gr < M) {
            int t = timei[gr];
            v = ((const float4*)(ttab + (size_t)t * 128))[c4];
        }
        float* ap = As + r * KP + 128 + c4 * 4;
        ap[0] = __uint_as_float(f2tf32(v.x));
        ap[1] = __uint_as_float(f2tf32(v.y));
        ap[2] = __uint_as_float(f2tf32(v.z));
        ap[3] = __uint_as_float(f2tf32(v.w));
    }

    // GEMM2: hidden = relu(cat(branch,t_emb) @ W_a1 + cadd)
#pragma unroll
    for (int mf = 0; mf < 2; ++mf)
#pragma unroll
        for (int nf = 0; nf < 8; ++nf)
#pragma unroll
            for (int j = 0; j < 4; ++j) acc[mf][nf][j] = 0.f;

    for (int kc = 0; kc < 2; ++kc) {
        __syncthreads();
        for (int i = tid; i < 128 * 32; i += 256) {
            int k = i >> 5, c4 = i & 31;
            float4 v = ((const float4*)(W_a1 + kc * 128 * 128))[i];
            float* wp = Ws + k * WNP + c4 * 4;
            wp[0] = __uint_as_float(f2tf32(v.x));
            wp[1] = __uint_as_float(f2tf32(v.y));
            wp[2] = __uint_as_float(f2tf32(v.z));
            wp[3] = __uint_as_float(f2tf32(v.w));
        }
        __syncthreads();
        mma_block_128(As, KP, kc * 128, Ws, wm, wn, gid, tig, acc);
    }

    // epilogue2: dot with W_a2 per row
    float p[2][2] = {{0.f, 0.f}, {0.f, 0.f}};
#pragma unroll
    for (int nf = 0; nf < 8; ++nf) {
        const int c = wn * 64 + nf * 8 + tig * 2;
        const float ca0 = cadd[c], ca1 = cadd[c + 1];
        const float w20 = W_a2[c], w21 = W_a2[c + 1];
#pragma unroll
        for (int mf = 0; mf < 2; ++mf)
#pragma unroll
            for (int h = 0; h < 2; ++h) {
                float v0 = fmaxf(acc[mf][nf][2 * h]     + ca0, 0.f);
                float v1 = fmaxf(acc[mf][nf][2 * h + 1] + ca1, 0.f);
                p[mf][h] += v0 * w20 + v1 * w21;
            }
    }
#pragma unroll
    for (int o = 1; o <= 2; o <<= 1)
#pragma unroll
        for (int mf = 0; mf < 2; ++mf)
#pragma unroll
            for (int h = 0; h < 2; ++h)
                p[mf][h] += __shfl_xor_sync(0xffffffffu, p[mf][h], o);

    __syncthreads();
    if (tig == 0) {
#pragma unroll
        for (int mf = 0; mf < 2; ++mf)
#pragma unroll
            for (int h = 0; h < 2; ++h)
                red[wn * 128 + wm * 32 + mf * 16 + h * 8 + gid] = p[mf][h];
    }
    __syncthreads();
    if (tid < 128) {
        int gr = row0 + tid;
        if (gr < M) out[gr] = red[tid] + red[128 + tid] + b_a2[0];
    }
}

// ---------------- GAT edge kernels ----------------
__device__ __forceinline__ void atomicMaxFloat(float* addr, float v)
{
    if (v >= 0.f) atomicMax((int*)addr, __float_as_int(v));
    else          atomicMin((unsigned int*)addr, __float_as_uint(v));
}

__global__ void edge_score_kernel(const int* __restrict__ src, const int* __restrict__ dst,
                                  const float* __restrict__ att)
{
    int e = (int)(((size_t)blockIdx.x * blockDim.x + threadIdx.x) >> 5);
    if (e >= NE) return;
    int ln = threadIdx.x & 31;
    int s = src[e], d = dst[e];
    const float* xls = g_xl + (size_t)s * 128;
    const float* xrd = g_xr + (size_t)d * 128;
    float p = 0.f;
#pragma unroll
    for (int j = 0; j < 4; ++j) {
        int hh = ln + 32 * j;
        float v = xls[hh] + xrd[hh];
        v = v > 0.f ? v : 0.2f * v;
        p += v * att[hh];
    }
#pragma unroll
    for (int o = 16; o > 0; o >>= 1) p += __shfl_xor_sync(0xffffffffu, p, o);
    if (ln == 0) { g_ae[e] = p; atomicMaxFloat(&g_amax[d], p); }
}

// fused exp + scatter: acc[d] += ex*xl[s], den[d] += ex
__global__ void edge_scatter_kernel(const int* __restrict__ src, const int* __restrict__ dst)
{
    int e = (int)(((size_t)blockIdx.x * blockDim.x + threadIdx.x) >> 5);
    if (e >= NE) return;
    int ln = threadIdx.x & 31;
    int s = src[e], d = dst[e];
    float ex = __expf(g_ae[e] - g_amax[d]);
    if (ln == 0) atomicAdd(&g_den[d], ex);
    const float* xls = g_xl + (size_t)s * 128;
    float* accd = g_acc + (size_t)d * 128;
#pragma unroll
    for (int j = 0; j < 4; ++j) {
        int hh = ln + 32 * j;
        atomicAdd(&accd[hh], ex * xls[hh]);
    }
}

// h += relu(acc/(den+eps) + bias), float4-vectorized
__global__ void update_kernel(const float* __restrict__ bias)
{
    size_t i = (size_t)blockIdx.x * blockDim.x + threadIdx.x;   // float4 index
    if (i >= (size_t)NN * 32) return;
    int node = (int)(i >> 5);
    int c4 = (int)(i & 31);
    float inv = 1.f / (g_den[node] + 1e-16f);
    float4 a = ((const float4*)g_acc)[i];
    float4 h = ((const float4*)g_h)[i];
    const float* bp = bias + c4 * 4;
    h.x += fmaxf(a.x * inv + bp[0], 0.f);
    h.y += fmaxf(a.y * inv + bp[1], 0.f);
    h.z += fmaxf(a.z * inv + bp[2], 0.f);
    h.w += fmaxf(a.w * inv + bp[3], 0.f);
    ((float4*)g_h)[i] = h;
}

// ---------------- context precompute ----------------
__global__ void ctx_kernel(const float* __restrict__ focal, const float* __restrict__ W_seq,
                           const float* __restrict__ b_seq)
{
    int j = threadIdx.x;
    float s = b_seq[j];
    for (int d = 0; d < DD; ++d) s += focal[d] * W_seq[d * 128 + j];
    g_ctx[j] = s;
}

__global__ void cadd_kernel(const float* __restrict__ W_a1, const float* __restrict__ b_a1)
{
    int j = threadIdx.x;
    float s = b_a1[j];
    for (int k = 0; k < 128; ++k) s += g_ctx[k] * W_a1[(256 + k) * 128 + j];
    g_cadd[j] = s;
}

// ---------------- launch ----------------
extern "C" void kernel_launch(void* const* d_in, const int* in_sizes, int n_in,
                              void* d_out, int out_size)
{
    const float* x       = (const float*)d_in[0];
    const int*   ei      = (const int*)  d_in[1];
    const float* focal   = (const float*)d_in[2];
    const int*   child   = (const int*)  d_in[3];
    const int*   parent  = (const int*)  d_in[4];
    const int*   timei   = (const int*)  d_in[5];
    const float* W_embed = (const float*)d_in[6];
    const float* b_embed = (const float*)d_in[7];
    const float* bu_Wl   = (const float*)d_in[8];
    const float* bu_bl   = (const float*)d_in[9];
    const float* bu_Wr   = (const float*)d_in[10];
    const float* bu_br   = (const float*)d_in[11];
    const float* bu_att  = (const float*)d_in[12];
    const float* bu_bias = (const float*)d_in[13];
    const float* td_Wl   = (const float*)d_in[14];
    const float* td_bl   = (const float*)d_in[15];
    const float* td_Wr   = (const float*)d_in[16];
    const float* td_br   = (const float*)d_in[17];
    const float* td_att  = (const float*)d_in[18];
    const float* td_bias = (const float*)d_in[19];
    const float* ttab    = (const float*)d_in[20];
    const float* W_comb  = (const float*)d_in[21];
    const float* b_comb  = (const float*)d_in[22];
    const float* W_a1    = (const float*)d_in[23];
    const float* b_a1    = (const float*)d_in[24];
    const float* W_a2    = (const float*)d_in[25];
    const float* b_a2    = (const float*)d_in[26];
    const float* W_seq   = (const float*)d_in[27];
    const float* b_seq   = (const float*)d_in[28];
    float* out = (float*)d_out;

    const int SM_EMB  = (BM * 68  + 64  * WNP) * 4;               // ~69.6 KB
    const int SM_DUAL = (BM * 132 + 2 * 128 * WNP) * 4;           // ~206.8 KB
    const int SM_HEAD = (BM * 260 + 128 * WNP + 256) * 4;         // ~203.8 KB
    cudaFuncSetAttribute(mm_embed,    cudaFuncAttributeMaxDynamicSharedMemorySize, SM_EMB);
    cudaFuncSetAttribute(mm_dual,     cudaFuncAttributeMaxDynamicSharedMemorySize, SM_DUAL);
    cudaFuncSetAttribute(head_kernel, cudaFuncAttributeMaxDynamicSharedMemorySize, SM_HEAD);

    float *hp, *xlp, *xrp, *accp, *amaxp, *denp, *caddp;
    cudaGetSymbolAddress((void**)&hp,    g_h);
    cudaGetSymbolAddress((void**)&xlp,   g_xl);
    cudaGetSymbolAddress((void**)&xrp,   g_xr);
    cudaGetSymbolAddress((void**)&accp,  g_acc);
    cudaGetSymbolAddress((void**)&amaxp, g_amax);
    cudaGetSymbolAddress((void**)&denp,  g_den);
    cudaGetSymbolAddress((void**)&caddp, g_cadd);

    const int GEMM_BLKS_N = (NN + BM - 1) / BM;
    const int GEMM_BLKS_A = (NA + BM - 1) / BM;
    const int UPD_BLKS    = (int)(((size_t)NN * 32 + 255) / 256);
    const int EDGE_W_BLKS = (NE + 7) / 8;

    // 1) embed
    mm_embed<<<GEMM_BLKS_N, 256, SM_EMB>>>(x, W_embed, b_embed, hp, NN);

    // 2) bottom-up GATv2: src = row1, dst = row0
    {
        const int* src = ei + NE;
        const int* dst = ei;
        mm_dual<<<GEMM_BLKS_N, 256, SM_DUAL>>>(hp, bu_Wl, bu_bl, xlp, bu_Wr, bu_br, xrp, NN);
        cudaMemsetAsync(accp,  0,    (size_t)NN * HH * 4);
        cudaMemsetAsync(denp,  0,    (size_t)NN * 4);
        cudaMemsetAsync(amaxp, 0xFF, (size_t)NN * 4);
        edge_score_kernel<<<EDGE_W_BLKS, 256>>>(src, dst, bu_att);
        edge_scatter_kernel<<<EDGE_W_BLKS, 256>>>(src, dst);
        update_kernel<<<UPD_BLKS, 256>>>(bu_bias);
    }

    // 3) top-down GATv2: src = row0, dst = row1
    {
        const int* src = ei;
        const int* dst = ei + NE;
        mm_dual<<<GEMM_BLKS_N, 256, SM_DUAL>>>(hp, td_Wl, td_bl, xlp, td_Wr, td_br, xrp, NN);
        cudaMemsetAsync(accp,  0,    (size_t)NN * HH * 4);
        cudaMemsetAsync(denp,  0,    (size_t)NN * 4);
        cudaMemsetAsync(amaxp, 0xFF, (size_t)NN * 4);
        edge_score_kernel<<<EDGE_W_BLKS, 256>>>(src, dst, td_att);
        edge_scatter_kernel<<<EDGE_W_BLKS, 256>>>(src, dst);
        update_kernel<<<UPD_BLKS, 256>>>(td_bias);
    }

    // 4) context fold
    ctx_kernel<<<1, 128>>>(focal, W_seq, b_seq);
    cadd_kernel<<<1, 128>>>(W_a1, b_a1);

    // 5) fused head: branch -> hidden -> logits
    head_kernel<<<GEMM_BLKS_A, 256, SM_HEAD>>>(hp, child, parent, ttab, timei,
                                               W_comb, b_comb, W_a1, caddp,
                                               W_a2, b_a2, out, NA);
}

// round 4
// speedup vs baseline: 2.0067x; 1.0485x over previous
#include <cuda_runtime.h>
#include <math.h>
#include <stdint.h>

#define NN   300000
#define NE   299999
#define NA   150000
#define DD   64
#define HH   128

// ---------------- scratch ----------------
__device__ float g_h   [(size_t)NN * HH];
__device__ float g_xl  [(size_t)NN * HH];
__device__ float g_xr  [(size_t)NN * HH];
__device__ float g_acc [(size_t)NN * HH];
__device__ float g_den [NN];
__device__ float g_ctx [HH];
__device__ float g_cadd[HH];

// ---------------- tf32 helpers ----------------
__device__ __forceinline__ uint32_t f2tf32(float f)
{
    uint32_t u;
    asm("cvt.rna.tf32.f32 %0, %1;" : "=r"(u) : "f"(f));
    return u;
}

__device__ __forceinline__ void mma_tf32(float* d, const uint32_t* a, const uint32_t* b)
{
    asm volatile(
        "mma.sync.aligned.m16n8k8.row.col.f32.tf32.tf32.f32 "
        "{%0,%1,%2,%3},{%4,%5,%6,%7},{%8,%9},{%0,%1,%2,%3};"
        : "+f"(d[0]), "+f"(d[1]), "+f"(d[2]), "+f"(d[3])
        : "r"(a[0]), "r"(a[1]), "r"(a[2]), "r"(a[3]), "r"(b[0]), "r"(b[1]));
}

#define BM  128
#define WNP 136
#define AP  132   // A pitch for K=128 staging

__device__ __forceinline__ void zero_acc(float acc[2][8][4])
{
#pragma unroll
    for (int mf = 0; mf < 2; ++mf)
#pragma unroll
        for (int nf = 0; nf < 8; ++nf)
#pragma unroll
            for (int j = 0; j < 4; ++j) acc[mf][nf][j] = 0.f;
}

__device__ __forceinline__ void mma_block_128(
    const float* As, int KP, int a_off, const float* Ws,
    int wm, int wn, int gid, int tig, float acc[2][8][4])
{
#pragma unroll
    for (int ks = 0; ks < 16; ++ks) {
        const int k0 = ks * 8;
        uint32_t a[2][4], b[8][2];
#pragma unroll
        for (int mf = 0; mf < 2; ++mf) {
            const float* ap = As + (wm * 32 + mf * 16 + gid) * KP + a_off + k0;
            a[mf][0] = __float_as_uint(ap[tig]);
            a[mf][1] = __float_as_uint(ap[8 * KP + tig]);
            a[mf][2] = __float_as_uint(ap[tig + 4]);
            a[mf][3] = __float_as_uint(ap[8 * KP + tig + 4]);
        }
#pragma unroll
        for (int nf = 0; nf < 8; ++nf) {
            const int c = wn * 64 + nf * 8 + gid;
            b[nf][0] = __float_as_uint(Ws[(k0 + tig) * WNP + c]);
            b[nf][1] = __float_as_uint(Ws[(k0 + tig + 4) * WNP + c]);
        }
#pragma unroll
        for (int mf = 0; mf < 2; ++mf)
#pragma unroll
            for (int nf = 0; nf < 8; ++nf)
                mma_tf32(acc[mf][nf], a[mf], b[nf]);
    }
}

__device__ __forceinline__ void stage_w128(const float* __restrict__ W, float* Ws, int tid)
{
    for (int i = tid; i < 128 * 32; i += 256) {
        int k = i >> 5, c4 = i & 31;
        float4 v = ((const float4*)W)[i];
        float* wp = Ws + k * WNP + c4 * 4;
        wp[0] = __uint_as_float(f2tf32(v.x));
        wp[1] = __uint_as_float(f2tf32(v.y));
        wp[2] = __uint_as_float(f2tf32(v.z));
        wp[3] = __uint_as_float(f2tf32(v.w));
    }
}

// ---------- fused embed + dual transform: h = x@We+be; xl=h@Wl+bl; xr=h@Wr+br ----------
__global__ __launch_bounds__(256) void embed_dual(
    const float* __restrict__ x,
    const float* __restrict__ We, const float* __restrict__ be,
    const float* __restrict__ Wl, const float* __restrict__ bl,
    const float* __restrict__ Wr, const float* __restrict__ br,
    float* __restrict__ Hout, float* __restrict__ Cl, float* __restrict__ Cr, int M)
{
    extern __shared__ float sh[];
    float* As  = sh;                 // BM x AP (phase A uses pitch 68)
    float* Ws0 = sh + BM * AP;
    float* Ws1 = Ws0 + 128 * WNP;
    const int tid = threadIdx.x;
    const int row0 = blockIdx.x * BM;

    // phase A: stage x (pitch 68) and W_embed
    for (int i = tid; i < 64 * 32; i += 256) {
        int k = i >> 5, c4 = i & 31;
        float4 v = ((const float4*)We)[i];
        float* wp = Ws0 + k * WNP + c4 * 4;
        wp[0] = __uint_as_float(f2tf32(v.x));
        wp[1] = __uint_as_float(f2tf32(v.y));
        wp[2] = __uint_as_float(f2tf32(v.z));
        wp[3] = __uint_as_float(f2tf32(v.w));
    }
    for (int i = tid; i < BM * 16; i += 256) {
        int r = i >> 4, c4 = i & 15;
        int gr = row0 + r;
        float4 v = make_float4(0.f, 0.f, 0.f, 0.f);
        if (gr < M) v = ((const float4*)(x + (size_t)gr * 64))[c4];
        float* ap = As + r * 68 + c4 * 4;
        ap[0] = __uint_as_float(f2tf32(v.x));
        ap[1] = __uint_as_float(f2tf32(v.y));
        ap[2] = __uint_as_float(f2tf32(v.z));
        ap[3] = __uint_as_float(f2tf32(v.w));
    }
    __syncthreads();

    const int wid = tid >> 5, lane = tid & 31;
    const int wm = wid & 3, wn = wid >> 2;
    const int gid = lane >> 2, tig = lane & 3;

    float acc[2][8][4];
    zero_acc(acc);
#pragma unroll
    for (int ks = 0; ks < 8; ++ks) {
        const int k0 = ks * 8;
        uint32_t a[2][4], b[8][2];
#pragma unroll
        for (int mf = 0; mf < 2; ++mf) {
            const float* ap = As + (wm * 32 + mf * 16 + gid) * 68 + k0;
            a[mf][0] = __float_as_uint(ap[tig]);
            a[mf][1] = __float_as_uint(ap[8 * 68 + tig]);
            a[mf][2] = __float_as_uint(ap[tig + 4]);
            a[mf][3] = __float_as_uint(ap[8 * 68 + tig + 4]);
        }
#pragma unroll
        for (int nf = 0; nf < 8; ++nf) {
            const int c = wn * 64 + nf * 8 + gid;
            b[nf][0] = __float_as_uint(Ws0[(k0 + tig) * WNP + c]);
            b[nf][1] = __float_as_uint(Ws0[(k0 + tig + 4) * WNP + c]);
        }
#pragma unroll
        for (int mf = 0; mf < 2; ++mf)
#pragma unroll
            for (int nf = 0; nf < 8; ++nf)
                mma_tf32(acc[mf][nf], a[mf], b[nf]);
    }
    __syncthreads();   // all reads of As/Ws0 complete

    // epilogue h: write gmem + restage tf32 into As (pitch AP)
#pragma unroll
    for (int nf = 0; nf < 8; ++nf) {
        const int c = wn * 64 + nf * 8 + tig * 2;
        const float b0 = be[c], b1 = be[c + 1];
#pragma unroll
        for (int mf = 0; mf < 2; ++mf)
#pragma unroll
            for (int h = 0; h < 2; ++h) {
                const int rl = wm * 32 + mf * 16 + h * 8 + gid;
                const float v0 = acc[mf][nf][2 * h] + b0;
                const float v1 = acc[mf][nf][2 * h + 1] + b1;
                const int gr = row0 + rl;
                if (gr < M)
                    *(float2*)(Hout + (size_t)gr * 128 + c) = make_float2(v0, v1);
                As[rl * AP + c]     = __uint_as_float(f2tf32(v0));
                As[rl * AP + c + 1] = __uint_as_float(f2tf32(v1));
            }
    }
    stage_w128(Wl, Ws0, tid);
    stage_w128(Wr, Ws1, tid);
    __syncthreads();

#pragma unroll
    for (int ph = 0; ph < 2; ++ph) {
        const float* Ws   = ph ? Ws1 : Ws0;
        const float* bias = ph ? br  : bl;
        float* C          = ph ? Cr  : Cl;
        zero_acc(acc);
        mma_block_128(As, AP, 0, Ws, wm, wn, gid, tig, acc);
#pragma unroll
        for (int nf = 0; nf < 8; ++nf) {
            const int c = wn * 64 + nf * 8 + tig * 2;
            const float b0 = bias[c], b1 = bias[c + 1];
#pragma unroll
            for (int mf = 0; mf < 2; ++mf)
#pragma unroll
                for (int h = 0; h < 2; ++h) {
                    const int r = row0 + wm * 32 + mf * 16 + h * 8 + gid;
                    if (r < M)
                        *(float2*)(C + (size_t)r * 128 + c) =
                            make_float2(acc[mf][nf][2 * h] + b0, acc[mf][nf][2 * h + 1] + b1);
                }
        }
    }
}

// ---------- dual transform with fused update: h1 = h + relu(acc/den + ubias) ----------
__global__ __launch_bounds__(256) void dual_upd(
    float* __restrict__ H, const float* __restrict__ Acc, const float* __restrict__ Den,
    const float* __restrict__ ubias,
    const float* __restrict__ Wl, const float* __restrict__ bl,
    const float* __restrict__ Wr, const float* __restrict__ br,
    float* __restrict__ Cl, float* __restrict__ Cr, int M)
{
    extern __shared__ float sh[];
    float* As  = sh;
    float* Ws0 = sh + BM * AP;
    float* Ws1 = Ws0 + 128 * WNP;
    const int tid = threadIdx.x;
    const int row0 = blockIdx.x * BM;

    stage_w128(Wl, Ws0, tid);
    stage_w128(Wr, Ws1, tid);

    for (int i = tid; i < BM * 32; i += 256) {
        int r = i >> 5, c4 = i & 31;
        int gr = row0 + r;
        float4 hv = make_float4(0.f, 0.f, 0.f, 0.f);
        if (gr < M) {
            float inv = 1.f / (Den[gr] + 1e-16f);
            float4 a = ((const float4*)Acc)[(size_t)gr * 32 + c4];
            hv = ((const float4*)H)[(size_t)gr * 32 + c4];
            const float4 bb = ((const float4*)ubias)[c4];
            hv.x += fmaxf(a.x * inv + bb.x, 0.f);
            hv.y += fmaxf(a.y * inv + bb.y, 0.f);
            hv.z += fmaxf(a.z * inv + bb.z, 0.f);
            hv.w += fmaxf(a.w * inv + bb.w, 0.f);
            ((float4*)H)[(size_t)gr * 32 + c4] = hv;
        }
        float* ap = As + r * AP + c4 * 4;
        ap[0] = __uint_as_float(f2tf32(hv.x));
        ap[1] = __uint_as_float(f2tf32(hv.y));
        ap[2] = __uint_as_float(f2tf32(hv.z));
        ap[3] = __uint_as_float(f2tf32(hv.w));
    }
    __syncthreads();

    const int wid = tid >> 5, lane = tid & 31;
    const int wm = wid & 3, wn = wid >> 2;
    const int gid = lane >> 2, tig = lane & 3;

    float acc[2][8][4];
#pragma unroll
    for (int ph = 0; ph < 2; ++ph) {
        const float* Ws   = ph ? Ws1 : Ws0;
        const float* bias = ph ? br  : bl;
        float* C          = ph ? Cr  : Cl;
        zero_acc(acc);
        mma_block_128(As, AP, 0, Ws, wm, wn, gid, tig, acc);
#pragma unroll
        for (int nf = 0; nf < 8; ++nf) {
            const int c = wn * 64 + nf * 8 + tig * 2;
            const float b0 = bias[c], b1 = bias[c + 1];
#pragma unroll
            for (int mf = 0; mf < 2; ++mf)
#pragma unroll
                for (int h = 0; h < 2; ++h) {
                    const int r = row0 + wm * 32 + mf * 16 + h * 8 + gid;
                    if (r < M)
                        *(float2*)(C + (size_t)r * 128 + c) =
                            make_float2(acc[mf][nf][2 * h] + b0, acc[mf][nf][2 * h + 1] + b1);
                }
        }
    }
}

// ---------- fused edge pass: score -> exp (no max shift) -> scatter ----------
__global__ void edge_kernel(const int* __restrict__ src, const int* __restrict__ dst,
                            const float* __restrict__ att)
{
    int e = (int)(((size_t)blockIdx.x * blockDim.x + threadIdx.x) >> 5);
    if (e >= NE) return;
    int ln = threadIdx.x & 31;
    int s = src[e], d = dst[e];
    float4 xa = ((const float4*)g_xl)[(size_t)s * 32 + ln];
    float4 xb = ((const float4*)g_xr)[(size_t)d * 32 + ln];
    float4 at = ((const float4*)att)[ln];
    float ex, ey, ez, ew;
    ex = xa.x + xb.x; ey = xa.y + xb.y; ez = xa.z + xb.z; ew = xa.w + xb.w;
    ex = ex > 0.f ? ex : 0.2f * ex;
    ey = ey > 0.f ? ey : 0.2f * ey;
    ez = ez > 0.f ? ez : 0.2f * ez;
    ew = ew > 0.f ? ew : 0.2f * ew;
    float p = ex * at.x + ey * at.y + ez * at.z + ew * at.w;
#pragma unroll
    for (int o = 16; o > 0; o >>= 1) p += __shfl_xor_sync(0xffffffffu, p, o);
    float e_ = __expf(p);
    if (ln == 0) atomicAdd(&g_den[d], e_);
    float* accd = g_acc + (size_t)d * 128 + ln * 4;
    atomicAdd(accd + 0, e_ * xa.x);
    atomicAdd(accd + 1, e_ * xa.y);
    atomicAdd(accd + 2, e_ * xa.z);
    atomicAdd(accd + 3, e_ * xa.w);
}

// ---------- mega head with on-the-fly update2 ----------
__global__ __launch_bounds__(256) void head_kernel(
    const float* __restrict__ H, const float* __restrict__ Acc, const float* __restrict__ Den,
    const float* __restrict__ ubias,
    const int* __restrict__ child, const int* __restrict__ parent,
    const float* __restrict__ ttab, const int* __restrict__ timei,
    const float* __restrict__ W_comb, const float* __restrict__ b_comb,
    const float* __restrict__ W_a1, const float* __restrict__ cadd,
    const float* __restrict__ W_a2, const float* __restrict__ b_a2,
    float* __restrict__ out, int M)
{
    constexpr int KP = 260;
    extern __shared__ float sh[];
    float* As  = sh;
    float* Ws  = sh + 128 * KP;
    float* red = Ws + 128 * WNP;
    const int tid = threadIdx.x;
    const int row0 = blockIdx.x * BM;

    // stage cat(h2[child], h2[parent]|0) with h2 = h1 + relu(acc/den + ubias)
    for (int i = tid; i < BM * 64; i += 256) {
        int r = i >> 6, c4 = i & 63;
        int gr = row0 + r;
        float4 v = make_float4(0.f, 0.f, 0.f, 0.f);
        if (gr < M) {
            int cc = c4 < 32 ? c4 : c4 - 32;
            int ri = c4 < 32 ? child[gr] : parent[gr];
            if (ri >= 0) {
                float inv = 1.f / (Den[ri] + 1e-16f);
                float4 a  = ((const float4*)Acc)[(size_t)ri * 32 + cc];
                v         = ((const float4*)H)[(size_t)ri * 32 + cc];
                float4 bb = ((const float4*)ubias)[cc];
                v.x += fmaxf(a.x * inv + bb.x, 0.f);
                v.y += fmaxf(a.y * inv + bb.y, 0.f);
                v.z += fmaxf(a.z * inv + bb.z, 0.f);
                v.w += fmaxf(a.w * inv + bb.w, 0.f);
            }
        }
        float* ap = As + r * KP + c4 * 4;
        ap[0] = __uint_as_float(f2tf32(v.x));
        ap[1] = __uint_as_float(f2tf32(v.y));
        ap[2] = __uint_as_float(f2tf32(v.z));
        ap[3] = __uint_as_float(f2tf32(v.w));
    }

    const int wid = tid >> 5, lane = tid & 31;
    const int wm = wid & 3, wn = wid >> 2;
    const int gid = lane >> 2, tig = lane & 3;

    float acc[2][8][4];
    zero_acc(acc);

    for (int kc = 0; kc < 2; ++kc) {
        __syncthreads();
        stage_w128(W_comb + kc * 128 * 128, Ws, tid);
        __syncthreads();
        mma_block_128(As, KP, kc * 128, Ws, wm, wn, gid, tig, acc);
    }
    __syncthreads();

#pragma unroll
    for (int nf = 0; nf < 8; ++nf) {
        const int c = wn * 64 + nf * 8 + tig * 2;
        const float b0 = b_comb[c], b1 = b_comb[c + 1];
#pragma unroll
        for (int mf = 0; mf < 2; ++mf)
#pragma unroll
            for (int h = 0; h < 2; ++h) {
                const int rl = wm * 32 + mf * 16 + h * 8 + gid;
                As[rl * KP + c]     = __uint_as_float(f2tf32(acc[mf][nf][2 * h]     + b0));
                As[rl * KP + c + 1] = __uint_as_float(f2tf32(acc[mf][nf][2 * h + 1] + b1));
            }
    }
    for (int i = tid; i < BM * 32; i += 256) {
        int r = i >> 5, c4 = i & 31;
        int gr = row0 + r;
        float4 v = make_float4(0.f, 0.f, 0.f, 0.f);
        if (gr < M) {
            int t = timei[gr];
            v = ((const float4*)(ttab + (size_t)t * 128))[c4];
        }
        float* ap = As + r * KP + 128 + c4 * 4;
        ap[0] = __uint_as_float(f2tf32(v.x));
        ap[1] = __uint_as_float(f2tf32(v.y));
        ap[2] = __uint_as_float(f2tf32(v.z));
        ap[3] = __uint_as_float(f2tf32(v.w));
    }

    zero_acc(acc);
    for (int kc = 0; kc < 2; ++kc) {
        __syncthreads();
        stage_w128(W_a1 + kc * 128 * 128, Ws, tid);
        __syncthreads();
        mma_block_128(As, KP, kc * 128, Ws, wm, wn, gid, tig, acc);
    }

    float p[2][2] = {{0.f, 0.f}, {0.f, 0.f}};
#pragma unroll
    for (int nf = 0; nf < 8; ++nf) {
        const int c = wn * 64 + nf * 8 + tig * 2;
        const float ca0 = cadd[c], ca1 = cadd[c + 1];
        const float w20 = W_a2[c], w21 = W_a2[c + 1];
#pragma unroll
        for (int mf = 0; mf < 2; ++mf)
#pragma unroll
            for (int h = 0; h < 2; ++h) {
                float v0 = fmaxf(acc[mf][nf][2 * h]     + ca0, 0.f);
                float v1 = fmaxf(acc[mf][nf][2 * h + 1] + ca1, 0.f);
                p[mf][h] += v0 * w20 + v1 * w21;
            }
    }
#pragma unroll
    for (int o = 1; o <= 2; o <<= 1)
#pragma unroll
        for (int mf = 0; mf < 2; ++mf)
#pragma unroll
            for (int h = 0; h < 2; ++h)
                p[mf][h] += __shfl_xor_sync(0xffffffffu, p[mf][h], o);

    __syncthreads();
    if (tig == 0) {
#pragma unroll
        for (int mf = 0; mf < 2; ++mf)
#pragma unroll
            for (int h = 0; h < 2; ++h)
                red[wn * 128 + wm * 32 + mf * 16 + h * 8 + gid] = p[mf][h];
    }
    __syncthreads();
    if (tid < 128) {
        int gr = row0 + tid;
        if (gr < M) out[gr] = red[tid] + red[128 + tid] + b_a2[0];
    }
}

// ---------------- context precompute ----------------
__global__ void ctx_kernel(const float* __restrict__ focal, const float* __restrict__ W_seq,
                           const float* __restrict__ b_seq)
{
    int j = threadIdx.x;
    float s = b_seq[j];
    for (int d = 0; d < DD; ++d) s += focal[d] * W_seq[d * 128 + j];
    g_ctx[j] = s;
}

__global__ void cadd_kernel(const float* __restrict__ W_a1, const float* __restrict__ b_a1)
{
    int j = threadIdx.x;
    float s = b_a1[j];
    for (int k = 0; k < 128; ++k) s += g_ctx[k] * W_a1[(256 + k) * 128 + j];
    g_cadd[j] = s;
}

// ---------------- launch ----------------
extern "C" void kernel_launch(void* const* d_in, const int* in_sizes, int n_in,
                              void* d_out, int out_size)
{
    const float* x       = (const float*)d_in[0];
    const int*   ei      = (const int*)  d_in[1];
    const float* focal   = (const float*)d_in[2];
    const int*   child   = (const int*)  d_in[3];
    const int*   parent  = (const int*)  d_in[4];
    const int*   timei   = (const int*)  d_in[5];
    const float* W_embed = (const float*)d_in[6];
    const float* b_embed = (const float*)d_in[7];
    const float* bu_Wl   = (const float*)d_in[8];
    const float* bu_bl   = (const float*)d_in[9];
    const float* bu_Wr   = (const float*)d_in[10];
    const float* bu_br   = (const float*)d_in[11];
    const float* bu_att  = (const float*)d_in[12];
    const float* bu_bias = (const float*)d_in[13];
    const float* td_Wl   = (const float*)d_in[14];
    const float* td_bl   = (const float*)d_in[15];
    const float* td_Wr   = (const float*)d_in[16];
    const float* td_br   = (const float*)d_in[17];
    const float* td_att  = (const float*)d_in[18];
    const float* td_bias = (const float*)d_in[19];
    const float* ttab    = (const float*)d_in[20];
    const float* W_comb  = (const float*)d_in[21];
    const float* b_comb  = (const float*)d_in[22];
    const float* W_a1    = (const float*)d_in[23];
    const float* b_a1    = (const float*)d_in[24];
    const float* W_a2    = (const float*)d_in[25];
    const float* b_a2    = (const float*)d_in[26];
    const float* W_seq   = (const float*)d_in[27];
    const float* b_seq   = (const float*)d_in[28];
    float* out = (float*)d_out;

    const int SM_DUAL = (BM * AP + 2 * 128 * WNP) * 4;         // ~206.8 KB
    const int SM_HEAD = (BM * 260 + 128 * WNP + 256) * 4;      // ~203.8 KB
    cudaFuncSetAttribute(embed_dual,  cudaFuncAttributeMaxDynamicSharedMemorySize, SM_DUAL);
    cudaFuncSetAttribute(dual_upd,    cudaFuncAttributeMaxDynamicSharedMemorySize, SM_DUAL);
    cudaFuncSetAttribute(head_kernel, cudaFuncAttributeMaxDynamicSharedMemorySize, SM_HEAD);

    float *hp, *xlp, *xrp, *accp, *denp, *caddp;
    cudaGetSymbolAddress((void**)&hp,    g_h);
    cudaGetSymbolAddress((void**)&xlp,   g_xl);
    cudaGetSymbolAddress((void**)&xrp,   g_xr);
    cudaGetSymbolAddress((void**)&accp,  g_acc);
    cudaGetSymbolAddress((void**)&denp,  g_den);
    cudaGetSymbolAddress((void**)&caddp, g_cadd);

    const int GEMM_BLKS_N = (NN + BM - 1) / BM;
    const int GEMM_BLKS_A = (NA + BM - 1) / BM;
    const int EDGE_BLKS   = (NE + 7) / 8;

    // 1) embed + bottom-up transforms (src = row1, dst = row0)
    embed_dual<<<GEMM_BLKS_N, 256, SM_DUAL>>>(x, W_embed, b_embed,
                                              bu_Wl, bu_bl, bu_Wr, bu_br,
                                              hp, xlp, xrp, NN);
    cudaMemsetAsync(accp, 0, (size_t)NN * HH * 4);
    cudaMemsetAsync(denp, 0, (size_t)NN * 4);
    edge_kernel<<<EDGE_BLKS, 256>>>(ei + NE, ei, bu_att);

    // 2) update1 fused + top-down transforms (src = row0, dst = row1)
    dual_upd<<<GEMM_BLKS_N, 256, SM_DUAL>>>(hp, accp, denp, bu_bias,
                                            td_Wl, td_bl, td_Wr, td_br,
                                            xlp, xrp, NN);
    cudaMemsetAsync(accp, 0, (size_t)NN * HH * 4);
    cudaMemsetAsync(denp, 0, (size_t)NN * 4);
    edge_kernel<<<EDGE_BLKS, 256>>>(ei, ei + NE, td_att);

    // 3) context fold
    ctx_kernel<<<1, 128>>>(focal, W_seq, b_seq);
    cadd_kernel<<<1, 128>>>(W_a1, b_a1);

    // 4) head with on-the-fly update2
    head_kernel<<<GEMM_BLKS_A, 256, SM_HEAD>>>(hp, accp, denp, td_bias,
                                               child, parent, ttab, timei,
                                               W_comb, b_comb, W_a1, caddp,
                                               W_a2, b_a2, out, NA);
}